// round 15
// baseline (speedup 1.0000x reference)
#include <cuda_runtime.h>

// Problem constants (fixed by setup_inputs)
#define V_N 1000000
#define F_N 4200000
#define T_STEPS 5
#define VW_N (V_N / 32)        // 31250 sv/av bitmask words
#define B_N  (VW_N * 4)        // 125000 sv/av bitmask bytes
#define F4_N (F_N / 4)         // 1,050,000 function groups (4 fns each)
#define QCAP 262144
#define SV_SMEM_BYTES ((VW_N + 1) * 4)   // +1 always-zero sentinel word
#define NB 148                 // one co-resident wave (1 block/SM via smem)
#define TPB 1024
#define NTH (NB * TPB)

// Per-function packed record: [0:20)=v0 [20:40)=v1 [40:60)=v2, [60..62]=signs.
// Dead/inactive => SENT: all three vars = V_N -> probes hit the zero sentinel byte.
#define SENT (0xF4240ULL | (0xF4240ULL << 20) | (0xF4240ULL << 40))
__device__ unsigned long long g_rec[F_N];     // 33.6 MB
// Per-variable state: bits [8:32) = deg, [0:8) = sdeg + 128.
__device__ unsigned int g_deg[V_N];           // 4 MB
__device__ unsigned int g_av_bits[VW_N];
__device__ unsigned int g_sv_bits[VW_N];      // write-once bits; stale harmless
__device__ int          g_stamp[V_N];
__device__ int          g_qv[(T_STEPS + 1) * QCAP];
__device__ int          g_qc[T_STEPS * QCAP];
__device__ int          g_nqv[T_STEPS + 1];
__device__ int          g_nqc[T_STEPS];
__device__ unsigned int g_barcnt[16];

static __device__ __forceinline__ bool bit_of(const unsigned int* bits, int i) {
    return (bits[i >> 5] >> (i & 31)) & 1u;
}
static __device__ __forceinline__ unsigned is_single(unsigned int w) {
    int dg = (int)(w >> 8);
    int sd = (int)(w & 0xFFu) - 128;
    return (dg == (sd < 0 ? -sd : sd)) ? 1u : 0u;
}

// One-shot grid barrier p. All NB blocks co-resident (1 block/SM, single wave).
// __threadfence (gpu scope -> CCTL.IVALL) also restores L1 coherence per phase.
static __device__ __forceinline__ void grid_bar(int p) {
    __syncthreads();
    if (threadIdx.x == 0) {
        __threadfence();
        atomicAdd(&g_barcnt[p], 1u);
        while (((volatile unsigned int*)g_barcnt)[p] < (unsigned)gridDim.x) { }
        __threadfence();
    }
    __syncthreads();
}

// ---------------------------------------------------------------------------
// Init: one thread per 8 variables (one av byte): vectorized stores/loads.
__global__ void k_init_v(const float* __restrict__ av_in) {
    int i = blockIdx.x * blockDim.x + threadIdx.x;   // byte index
    if (i < B_N) {
        uint4 d = make_uint4(128u, 128u, 128u, 128u);   // deg=0, sdeg=0(+bias)
        uint4 s = make_uint4(~0u, ~0u, ~0u, ~0u);       // stamp = -1
        reinterpret_cast<uint4*>(g_deg)[2 * i]     = d;
        reinterpret_cast<uint4*>(g_deg)[2 * i + 1] = d;
        reinterpret_cast<uint4*>(g_stamp)[2 * i]     = s;
        reinterpret_cast<uint4*>(g_stamp)[2 * i + 1] = s;
        const float4* ap = reinterpret_cast<const float4*>(av_in) + 2 * i;
        float4 a0 = __ldcs(ap), a1 = __ldcs(ap + 1);
        unsigned avb = ((a0.x != 0.0f) << 0) | ((a0.y != 0.0f) << 1)
                     | ((a0.z != 0.0f) << 2) | ((a0.w != 0.0f) << 3)
                     | ((a1.x != 0.0f) << 4) | ((a1.y != 0.0f) << 5)
                     | ((a1.z != 0.0f) << 6) | ((a1.w != 0.0f) << 7);
        reinterpret_cast<unsigned char*>(g_av_bits)[i] = (unsigned char)avb;
    }
    if (blockIdx.x == 0) {
        if (threadIdx.x < T_STEPS + 1) g_nqv[threadIdx.x] = 0;
        if (threadIdx.x < T_STEPS)     g_nqc[threadIdx.x] = 0;
        if (threadIdx.x < 16)          g_barcnt[threadIdx.x] = 0;
    }
}

// Build: 4 fns/thread; packed u64 records (coalesced) + deg/sdeg via RED32 only.
// Reads af_in directly; inactive fns pre-neutralized (SENT).
__global__ void k_build(const int* __restrict__ vidx, const float* __restrict__ ef,
                        const float* __restrict__ af_in) {
    int i = blockIdx.x * blockDim.x + threadIdx.x;
    if (i >= F4_N) return;
    const int4*   vp = reinterpret_cast<const int4*>(vidx) + 3 * i;
    const float4* fp = reinterpret_cast<const float4*>(ef) + 3 * i;
    int4   a = __ldcs(vp),     b = __ldcs(vp + 1),     c = __ldcs(vp + 2);
    float4 x = __ldcs(fp),     y = __ldcs(fp + 1),     z = __ldcs(fp + 2);
    float4 afv = __ldcs(reinterpret_cast<const float4*>(af_in) + i);
    int   vv[12] = {a.x, a.y, a.z, a.w, b.x, b.y, b.z, b.w, c.x, c.y, c.z, c.w};
    float ee[12] = {x.x, x.y, x.z, x.w, y.x, y.y, y.z, y.w, z.x, z.y, z.z, z.w};
    bool  af[4]  = {afv.x != 0.0f, afv.y != 0.0f, afv.z != 0.0f, afv.w != 0.0f};
    unsigned long long recs[4];
#pragma unroll
    for (int k = 0; k < 4; k++) {
        int v0 = vv[3 * k], v1 = vv[3 * k + 1], v2 = vv[3 * k + 2];
        unsigned long long s0 = ee[3 * k] > 0.0f, s1 = ee[3 * k + 1] > 0.0f,
                           s2 = ee[3 * k + 2] > 0.0f;
        if (af[k]) {
            recs[k] = (unsigned long long)(unsigned)v0
                    | ((unsigned long long)(unsigned)v1 << 20)
                    | ((unsigned long long)(unsigned)v2 << 40)
                    | (s0 << 60) | (s1 << 61) | (s2 << 62);
            atomicAdd(&g_deg[v0], (1u << 8) + (s0 ? 1u : 0xFFFFFFFFu));
            atomicAdd(&g_deg[v1], (1u << 8) + (s1 ? 1u : 0xFFFFFFFFu));
            atomicAdd(&g_deg[v2], (1u << 8) + (s2 ? 1u : 0xFFFFFFFFu));
        } else {
            recs[k] = SENT;
        }
    }
    ulonglong2* rp = reinterpret_cast<ulonglong2*>(g_rec) + 2 * i;
    rp[0] = make_ulonglong2(recs[0], recs[1]);
    rp[1] = make_ulonglong2(recs[2], recs[3]);
}

// ---- phases of the fused solve kernel -------------------------------------

// Full V scan: one thread per sv BYTE (8 vars, 2x uint4 deg loads), byte store,
// warp-aggregated enqueue into qv[0]. ~125K working threads (was 31K).
static __device__ __forceinline__ void var_full_phase() {
    int i = blockIdx.x * TPB + threadIdx.x;          // byte index
    int lane = threadIdx.x & 31;
    unsigned svb = 0;
    if (i < B_N) {
        unsigned avb = reinterpret_cast<const unsigned char*>(g_av_bits)[i];
        const uint4* dp = reinterpret_cast<const uint4*>(g_deg) + 2 * i;
        uint4 d0 = dp[0], d1 = dp[1];
        svb = (is_single(d0.x) << 0) | (is_single(d0.y) << 1)
            | (is_single(d0.z) << 2) | (is_single(d0.w) << 3)
            | (is_single(d1.x) << 4) | (is_single(d1.y) << 5)
            | (is_single(d1.z) << 6) | (is_single(d1.w) << 7);
        svb &= avb;
        reinterpret_cast<unsigned char*>(g_sv_bits)[i] = (unsigned char)svb;
    }
    int cnt = __popc(svb);
    int pre = cnt;
    for (int o = 1; o < 32; o <<= 1) {
        int n = __shfl_up_sync(0xffffffffu, pre, o);
        if (lane >= o) pre += n;
    }
    int total = __shfl_sync(0xffffffffu, pre, 31);
    if (total) {
        int base = 0;
        if (lane == 31) base = atomicAdd(&g_nqv[0], total);
        base = __shfl_sync(0xffffffffu, base, 31);
        int p = base + pre - cnt;
        unsigned mb = svb;
        while (mb) {
            int b = __ffs(mb) - 1; mb &= mb - 1;
            if (p < QCAP) g_qv[p] = 8 * i + b;
            p++;
        }
    }
}

// One record: probe 3 sv BYTES in smem (LDS.U8, no address scaling);
// on hit neutralize own rec + decrement still-active neighbors.
static __device__ __forceinline__ void do_rec(
    int t, bool final_t, int f, unsigned long long r,
    const unsigned char* sh8, int* lv, int& cnt)
{
    unsigned v0 = (unsigned)(r & 0xFFFFFULL);
    unsigned v1 = (unsigned)((r >> 20) & 0xFFFFFULL);
    unsigned v2 = (unsigned)((r >> 40) & 0xFFFFFULL);
    unsigned h = ((unsigned)sh8[v0 >> 3] >> (v0 & 7u))
               | ((unsigned)sh8[v1 >> 3] >> (v1 & 7u))
               | ((unsigned)sh8[v2 >> 3] >> (v2 & 7u));
    if (h & 1u) {
        if (!final_t) g_rec[f] = SENT;                // owner-only write
        unsigned vs[3] = {v0, v1, v2};
#pragma unroll
        for (int j = 0; j < 3; j++) {
            int v = (int)vs[j];
            if (bit_of(g_av_bits, v)) {               // pre-kill av gate
                unsigned long long s = (r >> (60 + j)) & 1ULL;
                atomicAdd(&g_deg[v], (unsigned)(-(int)((1u << 8) + (s ? 1 : -1))));
                if (!final_t && atomicExch(&g_stamp[v], t) != t)
                    lv[cnt++] = v;
            }
        }
    }
}

// Scan: 4 functions/thread (one ulonglong2 pair = 32B), byte sv probes.
static __device__ __forceinline__ void scan_phase(int t, const unsigned char* sh8,
                                                  bool final_t) {
    int gid = blockIdx.x * TPB + threadIdx.x;
    int lane = threadIdx.x & 31;
    for (int i = gid; __any_sync(0xffffffffu, i < F4_N); i += NTH) {
        int lv[12]; int cnt = 0;
        if (i < F4_N) {
            const ulonglong2* rp = reinterpret_cast<const ulonglong2*>(g_rec) + 2 * i;
            ulonglong2 r01 = __ldcs(rp), r23 = __ldcs(rp + 1);
            do_rec(t, final_t, 4 * i + 0, r01.x, sh8, lv, cnt);
            do_rec(t, final_t, 4 * i + 1, r01.y, sh8, lv, cnt);
            do_rec(t, final_t, 4 * i + 2, r23.x, sh8, lv, cnt);
            do_rec(t, final_t, 4 * i + 3, r23.y, sh8, lv, cnt);
        }
        if (!final_t) {                               // warp-aggregated enqueue
            unsigned m = __ballot_sync(0xffffffffu, cnt > 0);
            if (m) {
                int pre = cnt;
                for (int o = 1; o < 32; o <<= 1) {
                    int n = __shfl_up_sync(0xffffffffu, pre, o);
                    if (lane >= o) pre += n;
                }
                int total = __shfl_sync(0xffffffffu, pre, 31);
                int base = 0;
                if (lane == 31) base = atomicAdd(&g_nqc[t], total);
                base = __shfl_sync(0xffffffffu, base, 31);
                int p = base + pre - cnt;
                for (int q = 0; q < cnt; q++)
                    if (p + q < QCAP) g_qc[t * QCAP + p + q] = lv[q];
            }
        }
    }
}

// Kill iteration-t singletons; test candidates -> qv[t+1] + global sv bits.
static __device__ __forceinline__ void varstep_phase(int t) {
    int nv = g_nqv[t]; if (nv > QCAP) nv = QCAP;
    int nc = g_nqc[t]; if (nc > QCAP) nc = QCAP;
    int tot = nv + nc;
    int gid = blockIdx.x * TPB + threadIdx.x;
    for (int i = gid; i < tot; i += NTH) {
        if (i < nv) {
            int v = g_qv[t * QCAP + i];
            atomicAnd(&g_av_bits[v >> 5], ~(1u << (v & 31)));   // av *= (1 - single_v)
        } else {
            int v = g_qc[t * QCAP + (i - nv)];
            if (!bit_of(g_sv_bits, v) && bit_of(g_av_bits, v)) {
                if (is_single(g_deg[v])) {
                    atomicOr(&g_sv_bits[v >> 5], 1u << (v & 31));
                    int p = atomicAdd(&g_nqv[t + 1], 1);
                    if (p < QCAP) g_qv[(t + 1) * QCAP + p] = v;
                }
            }
        }
    }
}

// Fused solver: var_full + 5 scans + 4 varsteps + output, one launch.
__global__ __launch_bounds__(TPB, 1) void k_solve(float* __restrict__ out) {
    extern __shared__ unsigned int sh_sv[];
    const unsigned char* sh8 = reinterpret_cast<const unsigned char*>(sh_sv);
    int barid = 0;

    var_full_phase();
    grid_bar(barid++);

    for (int w = threadIdx.x; w <= VW_N; w += TPB)   // +1 zero sentinel word
        sh_sv[w] = (w < VW_N) ? g_sv_bits[w] : 0u;
    __syncthreads();

    for (int t = 0; t < T_STEPS; t++) {
        bool skip = false;
        if (t > 0) {
            varstep_phase(t - 1);
            grid_bar(barid++);
            int n = g_nqv[t]; if (n > QCAP) n = QCAP;   // OR in new singleton bits
            for (int i = threadIdx.x; i < n; i += TPB) {
                int v = g_qv[t * QCAP + i];
                atomicOr(&sh_sv[v >> 5], 1u << (v & 31));
            }
            __syncthreads();
            skip = (n == 0);                         // uniform across all blocks
        }
        if (!skip) scan_phase(t, sh8, t == T_STEPS - 1);
        if (t < T_STEPS - 1) grid_bar(barid++);
    }

    grid_bar(barid++);                                // all decrements done
    int gid = blockIdx.x * TPB + threadIdx.x;
    for (int v = gid; v < V_N; v += NTH)
        out[v] = (float)(g_deg[v] >> 8);
}

// ---------------------------------------------------------------------------
extern "C" void kernel_launch(void* const* d_in, const int* in_sizes, int n_in,
                              void* d_out, int out_size) {
    const int*   gm    = (const int*)d_in[0];    // graph_map row 0 = vidx
    const float* ef    = (const float*)d_in[1];
    const float* av_in = (const float*)d_in[2];
    const float* af_in = (const float*)d_in[3];
    float*       out   = (float*)d_out;

    const int TB = 256;

    cudaFuncSetAttribute(k_solve,
                         cudaFuncAttributeMaxDynamicSharedMemorySize, SV_SMEM_BYTES);

    k_init_v<<<(B_N + TB - 1) / TB, TB>>>(av_in);          // 1
    k_build <<<(F4_N + TB - 1) / TB, TB>>>(gm, ef, af_in); // 2
    k_solve <<<NB, TPB, SV_SMEM_BYTES>>>(out);             // 3
}

// round 17
// speedup vs baseline: 1.3706x; 1.3706x over previous
#include <cuda_runtime.h>

// Problem constants (fixed by setup_inputs)
#define V_N 1000000
#define F_N 4200000
#define T_STEPS 5
#define VW_N (V_N / 32)        // 31250 sv/av bitmask words
#define F4_N (F_N / 4)         // 1,050,000 function groups (4 fns each)
#define QCAP 262144
#define SV_SMEM_BYTES ((VW_N + 1) * 4)   // +1 always-zero sentinel word
#define NB 148                 // one co-resident wave (1 block/SM via smem)
#define TPB 1024
#define NTH (NB * TPB)

// Per-function packed record: [0:20)=v0 [20:40)=v1 [40:60)=v2, [60..62]=signs.
// Dead/inactive => SENT: all three vars = V_N -> probes hit the zero sentinel word.
#define SENT (0xF4240ULL | (0xF4240ULL << 20) | (0xF4240ULL << 40))
__device__ unsigned long long g_rec[F_N];     // 33.6 MB
// Per-variable state: bits [8:32) = deg, [0:8) = sdeg + 128.
__device__ unsigned int g_deg[V_N];           // 4 MB
__device__ unsigned int g_av_bits[VW_N];
__device__ unsigned int g_sv_bits[VW_N];      // write-once bits; stale harmless
__device__ int          g_stamp[V_N];         // NEVER re-initialized: generation tags
__device__ int          g_gen;                // bumped once per launch
__device__ int          g_qv[(T_STEPS + 1) * QCAP];
__device__ int          g_qc[T_STEPS * QCAP];
__device__ int          g_nqv[T_STEPS + 1];
__device__ int          g_nqc[T_STEPS];
__device__ unsigned int g_barcnt[16];

static __device__ __forceinline__ bool bit_of(const unsigned int* bits, int i) {
    return (bits[i >> 5] >> (i & 31)) & 1u;
}
static __device__ __forceinline__ bool is_single(unsigned int w) {
    int dg = (int)(w >> 8);
    int sd = (int)(w & 0xFFu) - 128;
    return dg == (sd < 0 ? -sd : sd);
}

// One-shot grid barrier p. All NB blocks co-resident (1 block/SM, single wave).
// __threadfence (gpu scope -> CCTL.IVALL) also restores L1 coherence per phase.
static __device__ __forceinline__ void grid_bar(int p) {
    __syncthreads();
    if (threadIdx.x == 0) {
        __threadfence();
        atomicAdd(&g_barcnt[p], 1u);
        while (((volatile unsigned int*)g_barcnt)[p] < (unsigned)gridDim.x) { }
        __threadfence();
    }
    __syncthreads();
}

// ---------------------------------------------------------------------------
__global__ void k_init_v(const float* __restrict__ av_in) {
    int v = blockIdx.x * blockDim.x + threadIdx.x;
    bool in = (v < V_N);
    bool av = false;
    if (in) {
        g_deg[v] = 128u;         // deg=0, sdeg=0 (+bias)  (stamp NOT touched)
        av = (av_in[v] != 0.0f);
    }
    unsigned m = __ballot_sync(0xffffffffu, av);
    if (in && (v & 31) == 0) g_av_bits[v >> 5] = m;
    if (blockIdx.x == 0) {
        if (threadIdx.x < T_STEPS + 1) g_nqv[threadIdx.x] = 0;
        if (threadIdx.x < T_STEPS)     g_nqc[threadIdx.x] = 0;
        if (threadIdx.x < 16)          g_barcnt[threadIdx.x] = 0;
        if (threadIdx.x == 0)          g_gen = g_gen + 1;   // fresh tag space
    }
}

// Build: 4 fns/thread; packed u64 records (coalesced) + deg/sdeg via RED32 only.
// Reads af_in directly; inactive fns pre-neutralized (SENT).
__global__ void k_build(const int* __restrict__ vidx, const float* __restrict__ ef,
                        const float* __restrict__ af_in) {
    int i = blockIdx.x * blockDim.x + threadIdx.x;
    if (i >= F4_N) return;
    const int4*   vp = reinterpret_cast<const int4*>(vidx) + 3 * i;
    const float4* fp = reinterpret_cast<const float4*>(ef) + 3 * i;
    int4   a = __ldcs(vp),     b = __ldcs(vp + 1),     c = __ldcs(vp + 2);
    float4 x = __ldcs(fp),     y = __ldcs(fp + 1),     z = __ldcs(fp + 2);
    float4 afv = __ldcs(reinterpret_cast<const float4*>(af_in) + i);
    int   vv[12] = {a.x, a.y, a.z, a.w, b.x, b.y, b.z, b.w, c.x, c.y, c.z, c.w};
    float ee[12] = {x.x, x.y, x.z, x.w, y.x, y.y, y.z, y.w, z.x, z.y, z.z, z.w};
    bool  af[4]  = {afv.x != 0.0f, afv.y != 0.0f, afv.z != 0.0f, afv.w != 0.0f};
    unsigned long long recs[4];
#pragma unroll
    for (int k = 0; k < 4; k++) {
        int v0 = vv[3 * k], v1 = vv[3 * k + 1], v2 = vv[3 * k + 2];
        unsigned long long s0 = ee[3 * k] > 0.0f, s1 = ee[3 * k + 1] > 0.0f,
                           s2 = ee[3 * k + 2] > 0.0f;
        if (af[k]) {
            recs[k] = (unsigned long long)(unsigned)v0
                    | ((unsigned long long)(unsigned)v1 << 20)
                    | ((unsigned long long)(unsigned)v2 << 40)
                    | (s0 << 60) | (s1 << 61) | (s2 << 62);
            atomicAdd(&g_deg[v0], (1u << 8) + (s0 ? 1u : 0xFFFFFFFFu));
            atomicAdd(&g_deg[v1], (1u << 8) + (s1 ? 1u : 0xFFFFFFFFu));
            atomicAdd(&g_deg[v2], (1u << 8) + (s2 ? 1u : 0xFFFFFFFFu));
        } else {
            recs[k] = SENT;
        }
    }
    ulonglong2* rp = reinterpret_cast<ulonglong2*>(g_rec) + 2 * i;
    rp[0] = make_ulonglong2(recs[0], recs[1]);
    rp[1] = make_ulonglong2(recs[2], recs[3]);
}

// ---- phases of the fused solve kernel -------------------------------------

// Full V scan: compute sv bits, seed qv[0] (warp-aggregated enqueue).
static __device__ __forceinline__ void var_full_phase() {
    const int WPB = (VW_N + NB - 1) / NB;   // 212 words/block
    int w = blockIdx.x * WPB + threadIdx.x;
    int lane = threadIdx.x & 31;
    unsigned svw = 0;
    if (threadIdx.x < WPB && w < VW_N) {
        unsigned avw = g_av_bits[w];
        const uint4* dp = reinterpret_cast<const uint4*>(g_deg) + (size_t)w * 8;
#pragma unroll
        for (int q = 0; q < 8; q++) {
            uint4 d = dp[q];
            svw |= (unsigned)is_single(d.x) << (q * 4 + 0);
            svw |= (unsigned)is_single(d.y) << (q * 4 + 1);
            svw |= (unsigned)is_single(d.z) << (q * 4 + 2);
            svw |= (unsigned)is_single(d.w) << (q * 4 + 3);
        }
        svw &= avw;
        g_sv_bits[w] = svw;
    }
    int cnt = __popc(svw);
    int pre = cnt;
    for (int o = 1; o < 32; o <<= 1) {
        int n = __shfl_up_sync(0xffffffffu, pre, o);
        if (lane >= o) pre += n;
    }
    int total = __shfl_sync(0xffffffffu, pre, 31);
    if (total) {
        int base = 0;
        if (lane == 31) base = atomicAdd(&g_nqv[0], total);
        base = __shfl_sync(0xffffffffu, base, 31);
        int p = base + pre - cnt;
        unsigned mb = svw;
        while (mb) {
            int b = __ffs(mb) - 1; mb &= mb - 1;
            if (p < QCAP) g_qv[p] = 32 * w + b;
            p++;
        }
    }
}

// One record: probe 3 smem sv bits (word granularity — measured optimum);
// on hit neutralize own rec + decrement still-active neighbors.
static __device__ __forceinline__ void do_rec(
    int tag, bool final_t, int f, unsigned long long r,
    const unsigned int* sh_sv, int* lv, int& cnt)
{
    int v0 = (int)(r & 0xFFFFFULL);
    int v1 = (int)((r >> 20) & 0xFFFFFULL);
    int v2 = (int)((r >> 40) & 0xFFFFFULL);
    bool hit = ((sh_sv[v0 >> 5] >> (v0 & 31)) & 1u)
             | ((sh_sv[v1 >> 5] >> (v1 & 31)) & 1u)
             | ((sh_sv[v2 >> 5] >> (v2 & 31)) & 1u);
    if (hit) {
        if (!final_t) g_rec[f] = SENT;                // owner-only write
        int vs[3] = {v0, v1, v2};
#pragma unroll
        for (int j = 0; j < 3; j++) {
            int v = vs[j];
            if (bit_of(g_av_bits, v)) {               // pre-kill av gate
                unsigned long long s = (r >> (60 + j)) & 1ULL;
                atomicAdd(&g_deg[v], (unsigned)(-(int)((1u << 8) + (s ? 1 : -1))));
                if (!final_t && atomicExch(&g_stamp[v], tag) != tag)
                    lv[cnt++] = v;
            }
        }
    }
}

// Scan: 4 functions/thread (one ulonglong2 pair = 32B), smem word probes.
static __device__ __forceinline__ void scan_phase(int t, int tag,
                                                  const unsigned int* sh_sv,
                                                  bool final_t) {
    int gid = blockIdx.x * TPB + threadIdx.x;
    int lane = threadIdx.x & 31;
    for (int i = gid; __any_sync(0xffffffffu, i < F4_N); i += NTH) {
        int lv[12]; int cnt = 0;
        if (i < F4_N) {
            const ulonglong2* rp = reinterpret_cast<const ulonglong2*>(g_rec) + 2 * i;
            ulonglong2 r01 = __ldcs(rp), r23 = __ldcs(rp + 1);
            do_rec(tag, final_t, 4 * i + 0, r01.x, sh_sv, lv, cnt);
            do_rec(tag, final_t, 4 * i + 1, r01.y, sh_sv, lv, cnt);
            do_rec(tag, final_t, 4 * i + 2, r23.x, sh_sv, lv, cnt);
            do_rec(tag, final_t, 4 * i + 3, r23.y, sh_sv, lv, cnt);
        }
        if (!final_t) {                               // warp-aggregated enqueue
            unsigned m = __ballot_sync(0xffffffffu, cnt > 0);
            if (m) {
                int pre = cnt;
                for (int o = 1; o < 32; o <<= 1) {
                    int n = __shfl_up_sync(0xffffffffu, pre, o);
                    if (lane >= o) pre += n;
                }
                int total = __shfl_sync(0xffffffffu, pre, 31);
                int base = 0;
                if (lane == 31) base = atomicAdd(&g_nqc[t], total);
                base = __shfl_sync(0xffffffffu, base, 31);
                int p = base + pre - cnt;
                for (int q = 0; q < cnt; q++)
                    if (p + q < QCAP) g_qc[t * QCAP + p + q] = lv[q];
            }
        }
    }
}

// Kill iteration-t singletons; test candidates -> qv[t+1] + global sv bits.
static __device__ __forceinline__ void varstep_phase(int t) {
    int nv = g_nqv[t]; if (nv > QCAP) nv = QCAP;
    int nc = g_nqc[t]; if (nc > QCAP) nc = QCAP;
    int tot = nv + nc;
    int gid = blockIdx.x * TPB + threadIdx.x;
    for (int i = gid; i < tot; i += NTH) {
        if (i < nv) {
            int v = g_qv[t * QCAP + i];
            atomicAnd(&g_av_bits[v >> 5], ~(1u << (v & 31)));   // av *= (1 - single_v)
        } else {
            int v = g_qc[t * QCAP + (i - nv)];
            if (!bit_of(g_sv_bits, v) && bit_of(g_av_bits, v)) {
                if (is_single(g_deg[v])) {
                    atomicOr(&g_sv_bits[v >> 5], 1u << (v & 31));
                    int p = atomicAdd(&g_nqv[t + 1], 1);
                    if (p < QCAP) g_qv[(t + 1) * QCAP + p] = v;
                }
            }
        }
    }
}

// Fused solver: var_full + 5 scans + 4 varsteps + output, one launch.
__global__ __launch_bounds__(TPB, 1) void k_solve(float* __restrict__ out) {
    extern __shared__ unsigned int sh_sv[];
    int barid = 0;
    int gen = g_gen;                                  // stable for whole launch

    var_full_phase();
    grid_bar(barid++);

    for (int w = threadIdx.x; w <= VW_N; w += TPB)   // +1 zero sentinel word
        sh_sv[w] = (w < VW_N) ? g_sv_bits[w] : 0u;
    __syncthreads();

    for (int t = 0; t < T_STEPS; t++) {
        bool skip = false;
        if (t > 0) {
            varstep_phase(t - 1);
            grid_bar(barid++);
            int n = g_nqv[t]; if (n > QCAP) n = QCAP;   // OR in new singleton bits
            for (int i = threadIdx.x; i < n; i += TPB) {
                int v = g_qv[t * QCAP + i];
                atomicOr(&sh_sv[v >> 5], 1u << (v & 31));
            }
            __syncthreads();
            skip = (n == 0);                         // uniform across all blocks
        }
        if (!skip) scan_phase(t, gen * 8 + t, sh_sv, t == T_STEPS - 1);
        if (t < T_STEPS - 1) grid_bar(barid++);
    }

    grid_bar(barid++);                                // all decrements done
    int gid = blockIdx.x * TPB + threadIdx.x;
    for (int v = gid; v < V_N; v += NTH)
        out[v] = (float)(g_deg[v] >> 8);
}

// ---------------------------------------------------------------------------
extern "C" void kernel_launch(void* const* d_in, const int* in_sizes, int n_in,
                              void* d_out, int out_size) {
    const int*   gm    = (const int*)d_in[0];    // graph_map row 0 = vidx
    const float* ef    = (const float*)d_in[1];
    const float* av_in = (const float*)d_in[2];
    const float* af_in = (const float*)d_in[3];
    float*       out   = (float*)d_out;

    const int TB = 256;

    cudaFuncSetAttribute(k_solve,
                         cudaFuncAttributeMaxDynamicSharedMemorySize, SV_SMEM_BYTES);

    k_init_v<<<(V_N + TB - 1) / TB, TB>>>(av_in);          // 1
    k_build <<<(F4_N + TB - 1) / TB, TB>>>(gm, ef, af_in); // 2
    k_solve <<<NB, TPB, SV_SMEM_BYTES>>>(out);             // 3
}